// round 12
// baseline (speedup 1.0000x reference)
#include <cuda_runtime.h>
#include <math.h>

#define TPB     128
#define NGROUPS 4
#define GSIZE   32                // l-chunks per block
#define CHUNK   32                // l's per thread
#define NPACK   (CHUNK / 2)       // 16 packed f32x2 accumulators
#define MAXD    512
#define MAXN    64

// per-(d,n) constant block: 4 x float4 = 64 B
__device__ float4 gConst[MAXD * MAXN * 4];

// ---- packed f32x2 helpers (PTX-only) ----
__device__ __forceinline__ unsigned long long pack2(float lo, float hi) {
    unsigned long long r;
    asm("mov.b64 %0, {%1, %2};" : "=l"(r) : "f"(lo), "f"(hi));
    return r;
}
__device__ __forceinline__ void unpack2(unsigned long long v, float& lo, float& hi) {
    asm("mov.b64 {%0, %1}, %2;" : "=f"(lo), "=f"(hi) : "l"(v));
}
__device__ __forceinline__ unsigned long long fma2(unsigned long long a,
                                                   unsigned long long b,
                                                   unsigned long long c) {
    unsigned long long d;
    asm("fma.rn.f32x2 %0, %1, %2, %3;" : "=l"(d) : "l"(a), "l"(b), "l"(c));
    return d;
}
__device__ __forceinline__ unsigned long long mul2(unsigned long long a,
                                                   unsigned long long b) {
    unsigned long long d;
    asm("mul.rn.f32x2 %0, %1, %2;" : "=l"(d) : "l"(a), "l"(b));
    return d;
}
__device__ __forceinline__ unsigned long long add2(unsigned long long a,
                                                   unsigned long long b) {
    unsigned long long d;
    asm("add.rn.f32x2 %0, %1, %2;" : "=l"(d) : "l"(a), "l"(b));
    return d;
}

// 3-term Cody-Waite reduction of x mod 2*pi (exact FMAs for q <= ~8K)
__device__ __forceinline__ float reduce_2pi(float x) {
    const float INV2PI = 0.15915494309189535f;
    const float C1 = 6.28125f;
    const float C2 = 0.0019350051879882812f;
    const float C3 = 3.0197e-7f;
    float q = rintf(x * INV2PI);
    float r = fmaf(q, -C1, x);
    r = fmaf(q, -C2, r);
    r = fmaf(q, -C3, r);
    return r;
}

// ======================= pre-kernel: per-(d,n) constants =====================
__global__ void lssl_prep_kernel(
    const float* __restrict__ Lre, const float* __restrict__ Lim,
    const float* __restrict__ Bre, const float* __restrict__ Bim,
    const float* __restrict__ Cre, const float* __restrict__ Cim,
    const float* __restrict__ logdt, int N)
{
    const int d = blockIdx.x;
    const int n = threadIdx.x;
    if (n >= N) return;
    const int idx = d * N + n;

    float lr = Lre[idx], li = Lim[idx];
    float sp = fmaxf(lr, 0.0f) + log1pf(expf(-fabsf(lr)));  // softplus
    float lam_re = -sp, lam_im = li;
    float dt = expf(logdt[d]);

    float hre = 0.5f * dt * lam_re;
    float him = 0.5f * dt * lam_im;
    float dre = 1.0f - hre;
    float dim = -him;
    float inv = 1.0f / (dre * dre + dim * dim);

    float nre = 1.0f + hre, nim = him;
    float are = (nre * dre + nim * dim) * inv;   // a_bar
    float aim = (nim * dre - nre * dim) * inv;

    float br = Bre[idx], bi = Bim[idx];
    float bbre = dt * inv * (br * dre + bi * dim);
    float bbim = dt * inv * (bi * dre - br * dim);
    float cr = Cre[idx], ci = Cim[idx];
    float wre = cr * bbre - ci * bbim;           // w = C*b_bar
    float wim = cr * bbim + ci * bbre;

    float mag2 = are * are + aim * aim;
    float tr  = are + are;                       // 2 Re(a)
    float det = -mag2;                           // -|a|^2
    float tr2  = fmaf(tr, tr, 2.0f * det);       // stride-2 coeffs
    float det2 = -det * det;
    float tr4  = fmaf(tr2, tr2, 2.0f * det2);    // stride-4 coeffs
    float det4 = -det2 * det2;

    float wmag2 = wre * wre + wim * wim;
    float4* p = gConst + (d * N + n) * 4;
    p[0] = make_float4(0.5f * logf(mag2), atan2f(aim, are),
                       0.5f * logf(wmag2), atan2f(wim, wre));
    p[1] = make_float4(are, aim, tr, det);
    p[2] = make_float4(tr2, tr2, det2, det2);
    p[3] = make_float4(tr4, tr4, det4, det4);
}

// ======================= main kernel ========================================
__global__ void __launch_bounds__(TPB, 7)
lssl_main_kernel(
    const float* __restrict__ Dp,
    float* __restrict__ out, int N, int L, int d_model)
{
    // dynamic smem: 4 x float4 (=64B) per n, contiguous
    extern __shared__ float4 S[];

    __shared__ unsigned long long bufA[GSIZE][NPACK + 1];
    __shared__ unsigned long long bufB[GSIZE][NPACK + 1];

    const int d = blockIdx.x;
    const int t = threadIdx.x;

    // ---- Phase 1: pull constants from global scratch (L2-hot) ----
    {
        const float4* src = gConst + d * N * 4;
        for (int i = t; i < N * 4; i += TPB) S[i] = __ldg(src + i);
    }

    if (blockIdx.y == 0 && t == 0) {
        out[(size_t)d_model * (size_t)L + d] = Dp[d];  // D passthrough
    }
    __syncthreads();

    // ---- Phase 2: NGROUPS n-groups over this block's l-range ----
    const int grp = t / GSIZE;
    const int tg  = t % GSIZE;
    const int l0  = (blockIdx.y * GSIZE + tg) * CHUNK;
    const int nper = N / NGROUPS;
    const int n_begin = grp * nper;
    const int n_end   = n_begin + nper;

    unsigned long long acc[NPACK];
#pragma unroll
    for (int m = 0; m < NPACK; m++) acc[m] = 0ull;

    if (l0 < L) {
        const float fl0 = (float)l0;

        for (int n = n_begin; n < n_end; n++) {
            const float4* p = S + (n << 2);
            const ulonglong2* pc = (const ulonglong2*)p;
            const float4 A  = p[0];
            const float4 B4 = p[1];
            const ulonglong2 c2 = pc[2];   // (tr2p, det2p)
            const ulonglong2 c4 = pc[3];   // (tr4p, det4p)

            // seed: q = w * a^{l0} via fused log-magnitude + phase
            float e  = __expf(fmaf(fl0, A.x, A.z));
            float ph = reduce_2pi(fl0 * A.y) + A.w;
            float sn, cs;
            __sincosf(ph, &sn, &cs);
            float qre = e * cs, qim = e * sn;

            float s0 = qre;
            float s1 = fmaf(qre, B4.x, -(qim * B4.y));
            float s2 = fmaf(B4.z, s1, B4.w * s0);
            float s3 = fmaf(B4.z, s2, B4.w * s1);

            unsigned long long u0 = pack2(s0, s1);
            unsigned long long u1 = pack2(s2, s3);
            unsigned long long u2 = fma2(c2.x, u1, mul2(c2.y, u0));
            unsigned long long u3 = fma2(c2.x, u2, mul2(c2.y, u1));

            acc[0] = add2(acc[0], u0);
            acc[1] = add2(acc[1], u1);
            acc[2] = add2(acc[2], u2);
            acc[3] = add2(acc[3], u3);

            // twin independent stride-4 chains
            unsigned long long v_prev = u0, v_cur = u2;
            unsigned long long w_prev = u1, w_cur = u3;
#pragma unroll
            for (int m = 2; m < NPACK / 2; m++) {
                unsigned long long v_next = fma2(c4.x, v_cur, mul2(c4.y, v_prev));
                unsigned long long w_next = fma2(c4.x, w_cur, mul2(c4.y, w_prev));
                acc[2 * m]     = add2(acc[2 * m],     v_next);
                acc[2 * m + 1] = add2(acc[2 * m + 1], w_next);
                v_prev = v_cur; v_cur = v_next;
                w_prev = w_cur; w_cur = w_next;
            }
        }
    }

    // ---- 2-stage tree reduction: (g2->g0, g3->g1), then g1->g0 ----
    if (grp == 2) {
#pragma unroll
        for (int m = 0; m < NPACK; m++) bufA[tg][m] = acc[m];
    } else if (grp == 3) {
#pragma unroll
        for (int m = 0; m < NPACK; m++) bufB[tg][m] = acc[m];
    }
    __syncthreads();

    if (grp == 0) {
#pragma unroll
        for (int m = 0; m < NPACK; m++) acc[m] = add2(acc[m], bufA[tg][m]);
    } else if (grp == 1) {
#pragma unroll
        for (int m = 0; m < NPACK; m++) acc[m] = add2(acc[m], bufB[tg][m]);
    }
    __syncthreads();

    if (grp == 1) {
#pragma unroll
        for (int m = 0; m < NPACK; m++) bufA[tg][m] = acc[m];
    }
    __syncthreads();

    if (grp == 0 && l0 < L) {
#pragma unroll
        for (int m = 0; m < NPACK; m++) acc[m] = add2(acc[m], bufA[tg][m]);

        float* Kout = out + (size_t)d * (size_t)L + l0;
        if (l0 + CHUNK <= L) {
#pragma unroll
            for (int m = 0; m < NPACK; m++) {
                *reinterpret_cast<unsigned long long*>(Kout + 2 * m) = acc[m];
            }
        } else {
#pragma unroll
            for (int m = 0; m < NPACK; m++) {
                float lo, hi;
                unpack2(acc[m], lo, hi);
                if (l0 + 2 * m     < L) Kout[2 * m]     = lo;
                if (l0 + 2 * m + 1 < L) Kout[2 * m + 1] = hi;
            }
        }
    }
}

extern "C" void kernel_launch(void* const* d_in, const int* in_sizes, int n_in,
                              void* d_out, int out_size)
{
    const float* Lre   = (const float*)d_in[0];
    const float* Lim   = (const float*)d_in[1];
    const float* Bre   = (const float*)d_in[2];
    const float* Bim   = (const float*)d_in[3];
    const float* Cre   = (const float*)d_in[4];
    const float* Cim   = (const float*)d_in[5];
    const float* Dp    = (const float*)d_in[6];
    const float* logdt = (const float*)d_in[7];
    float* out = (float*)d_out;

    const int d_model = in_sizes[6];                 // 512
    const int N = in_sizes[0] / d_model;             // 64
    const int L = (out_size - d_model) / d_model;    // 2048

    static int attrs_set = 0;
    if (!attrs_set) {
        cudaFuncSetAttribute(lssl_main_kernel,
                             cudaFuncAttributePreferredSharedMemoryCarveout, 100);
        attrs_set = 1;
    }

    // 1) per-(d,n) constants
    lssl_prep_kernel<<<d_model, MAXN>>>(Lre, Lim, Bre, Bim, Cre, Cim, logdt, N);

    // 2) main compute
    const int per_block_l = GSIZE * CHUNK;           // 1024
    const int gridy = (L + per_block_l - 1) / per_block_l;  // 2
    dim3 grid(d_model, gridy);
    size_t shm = (size_t)N * 4 * sizeof(float4);     // 64B per n = 4KB
    lssl_main_kernel<<<grid, TPB, shm>>>(Dp, out, N, L, d_model);
}

// round 13
// speedup vs baseline: 1.1404x; 1.1404x over previous
#include <cuda_runtime.h>
#include <math.h>

#define TPB     128
#define NGROUPS 4
#define GSIZE   32                // l-chunks per block
#define CHUNK   32                // l's per thread
#define NPACK   (CHUNK / 2)       // 16 packed f32x2 accumulators

// ---- packed f32x2 helpers (PTX-only) ----
__device__ __forceinline__ unsigned long long pack2(float lo, float hi) {
    unsigned long long r;
    asm("mov.b64 %0, {%1, %2};" : "=l"(r) : "f"(lo), "f"(hi));
    return r;
}
__device__ __forceinline__ void unpack2(unsigned long long v, float& lo, float& hi) {
    asm("mov.b64 {%0, %1}, %2;" : "=f"(lo), "=f"(hi) : "l"(v));
}
__device__ __forceinline__ unsigned long long fma2(unsigned long long a,
                                                   unsigned long long b,
                                                   unsigned long long c) {
    unsigned long long d;
    asm("fma.rn.f32x2 %0, %1, %2, %3;" : "=l"(d) : "l"(a), "l"(b), "l"(c));
    return d;
}
__device__ __forceinline__ unsigned long long mul2(unsigned long long a,
                                                   unsigned long long b) {
    unsigned long long d;
    asm("mul.rn.f32x2 %0, %1, %2;" : "=l"(d) : "l"(a), "l"(b));
    return d;
}
__device__ __forceinline__ unsigned long long add2(unsigned long long a,
                                                   unsigned long long b) {
    unsigned long long d;
    asm("add.rn.f32x2 %0, %1, %2;" : "=l"(d) : "l"(a), "l"(b));
    return d;
}

// 3-term Cody-Waite reduction of x mod 2*pi (exact FMAs for q <= ~8K)
__device__ __forceinline__ float reduce_2pi(float x) {
    const float INV2PI = 0.15915494309189535f;
    const float C1 = 6.28125f;
    const float C2 = 0.0019350051879882812f;
    const float C3 = 3.0197e-7f;
    float q = rintf(x * INV2PI);
    float r = fmaf(q, -C1, x);
    r = fmaf(q, -C2, r);
    r = fmaf(q, -C3, r);
    return r;
}

__global__ void __launch_bounds__(TPB, 7)
lssl_fold_kernel(
    const float* __restrict__ Lre, const float* __restrict__ Lim,
    const float* __restrict__ Bre, const float* __restrict__ Bim,
    const float* __restrict__ Cre, const float* __restrict__ Cim,
    const float* __restrict__ Dp,  const float* __restrict__ logdt,
    float* __restrict__ out, int N, int L, int d_model)
{
    // dynamic smem: 4 x float4 (=64B) per n:
    //  [0] A  = (log|a|, arg a, log|w|, arg w)
    //  [1] B4 = (a.re, a.im, invc, det)
    //  [2] (tr2,tr2,det2,det2)
    //  [3] (trp,trp,-trp,-trp)
    extern __shared__ float4 S[];

    __shared__ unsigned long long bufA[GSIZE][NPACK + 1];
    __shared__ unsigned long long bufB[GSIZE][NPACK + 1];

    const int d = blockIdx.x;
    const int t = threadIdx.x;

    // ---- Phase 1: per-(d,n) constants ----
    for (int n = t; n < N; n += TPB) {
        const int idx = d * N + n;
        float lr = Lre[idx], li = Lim[idx];
        float sp = fmaxf(lr, 0.0f) + log1pf(expf(-fabsf(lr)));  // softplus
        float lam_re = -sp, lam_im = li;
        float dt = expf(logdt[d]);

        float hre = 0.5f * dt * lam_re;
        float him = 0.5f * dt * lam_im;
        float dre = 1.0f - hre;
        float dim = -him;
        float inv = 1.0f / (dre * dre + dim * dim);

        float nre = 1.0f + hre, nim = him;
        float are = (nre * dre + nim * dim) * inv;   // a_bar
        float aim = (nim * dre - nre * dim) * inv;

        float br = Bre[idx], bi = Bim[idx];
        float bbre = dt * inv * (br * dre + bi * dim);
        float bbim = dt * inv * (bi * dre - br * dim);
        float cr = Cre[idx], ci = Cim[idx];
        float wre = cr * bbre - ci * bbim;           // w = C*b_bar
        float wim = cr * bbim + ci * bbre;

        float mag2 = are * are + aim * aim;
        float tr  = are + are;                       // 2 Re(a)
        float det = -mag2;                           // -|a|^2
        float tr2  = fmaf(tr, tr, 2.0f * det);       // stride-2 coeffs
        float det2 = -det * det;
        float tr4  = fmaf(tr2, tr2, 2.0f * det2);    // stride-4 trace

        float c1   = det * det;                      // c = |a|^4
        float invc = 1.0f / c1;
        float trp  = tr4 * invc;

        float wmag2 = wre * wre + wim * wim;
        float4* p = S + (n << 2);
        p[0] = make_float4(0.5f * logf(mag2), atan2f(aim, are),
                           0.5f * logf(wmag2), atan2f(wim, wre));
        p[1] = make_float4(are, aim, invc, det);
        p[2] = make_float4(tr2, tr2, det2, det2);
        p[3] = make_float4(trp, trp, -trp, -trp);
    }

    if (blockIdx.y == 0 && t == 0) {
        out[(size_t)d_model * (size_t)L + d] = Dp[d];  // D passthrough
    }
    __syncthreads();

    // ---- Phase 2: NGROUPS n-groups over this block's l-range ----
    const int grp = t / GSIZE;
    const int tg  = t % GSIZE;
    const int l0  = (blockIdx.y * GSIZE + tg) * CHUNK;
    const int nper = N / NGROUPS;
    const int n_begin = grp * nper;
    const int n_end   = n_begin + nper;

    unsigned long long acc[NPACK];
#pragma unroll
    for (int m = 0; m < NPACK; m++) acc[m] = 0ull;

    if (l0 < L) {
        const float fl0 = (float)l0;

        for (int n = n_begin; n < n_end; n++) {
            const float4* p = S + (n << 2);
            const ulonglong2* pc = (const ulonglong2*)p;
            const float4 A  = p[0];
            const float4 B4 = p[1];            // (are, aim, invc, det)
            const ulonglong2 c2 = pc[2];       // (tr2p, det2p)
            const ulonglong2 tp = pc[3];       // (+trpP, -trpP)

            // seed: q = w * a^{l0} via fused log-magnitude + phase
            float e  = __expf(fmaf(fl0, A.x, A.z));
            float ph = reduce_2pi(fl0 * A.y) + A.w;
            float sn, cs;
            __sincosf(ph, &sn, &cs);
            float qre = e * cs, qim = e * sn;

            const float det = B4.w;
            const float tr  = B4.x + B4.x;

            float s0 = qre;
            float s1 = fmaf(qre, B4.x, -(qim * B4.y));
            float s2 = fmaf(tr, s1, det * s0);
            float s3 = fmaf(tr, s2, det * s1);

            unsigned long long u0 = pack2(s0, s1);
            unsigned long long u1 = pack2(s2, s3);
            unsigned long long u2 = fma2(c2.x, u1, mul2(c2.y, u0));
            unsigned long long u3 = fma2(c2.x, u2, mul2(c2.y, u1));

            acc[0] = add2(acc[0], u0);
            acc[1] = add2(acc[1], u1);
            acc[2] = add2(acc[2], u2);
            acc[3] = add2(acc[3], u3);

            // twin sign-folded scaled chains:
            //   g_{j+1} = (-/+trp)*g_j + g_{j-1};  acc_m += cs_j * g_j
            //   cs rolls: cs2=-c^2, cs3=cs2*c, cs4=-(cs3*c), cs5=cs4*c, ...
            const unsigned long long invcP = pack2(B4.z, B4.z);
            unsigned long long gv1 = mul2(u2, invcP);
            unsigned long long gw1 = mul2(u3, invcP);

            const float cv = det * det;          // c = |a|^4
            float csr = -(cv * cv);              // cs2
            unsigned long long csP = pack2(csr, csr);

            unsigned long long gv2 = fma2(tp.y, gv1, u0);     // -trp
            unsigned long long gw2 = fma2(tp.y, gw1, u1);
            acc[4] = fma2(csP, gv2, acc[4]);
            acc[5] = fma2(csP, gw2, acc[5]);

            csr = csr * cv;                      // cs3 = -c^3
            csP = pack2(csr, csr);
            unsigned long long gv3 = fma2(tp.x, gv2, gv1);    // +trp
            unsigned long long gw3 = fma2(tp.x, gw2, gw1);
            acc[6] = fma2(csP, gv3, acc[6]);
            acc[7] = fma2(csP, gw3, acc[7]);

            csr = -(csr * cv);                   // cs4 = +c^4
            csP = pack2(csr, csr);
            unsigned long long gv4 = fma2(tp.y, gv3, gv2);    // -trp
            unsigned long long gw4 = fma2(tp.y, gw3, gw2);
            acc[8] = fma2(csP, gv4, acc[8]);
            acc[9] = fma2(csP, gw4, acc[9]);

            csr = csr * cv;                      // cs5 = +c^5
            csP = pack2(csr, csr);
            unsigned long long gv5 = fma2(tp.x, gv4, gv3);    // +trp
            unsigned long long gw5 = fma2(tp.x, gw4, gw3);
            acc[10] = fma2(csP, gv5, acc[10]);
            acc[11] = fma2(csP, gw5, acc[11]);

            csr = -(csr * cv);                   // cs6 = -c^6
            csP = pack2(csr, csr);
            unsigned long long gv6 = fma2(tp.y, gv5, gv4);    // -trp
            unsigned long long gw6 = fma2(tp.y, gw5, gw4);
            acc[12] = fma2(csP, gv6, acc[12]);
            acc[13] = fma2(csP, gw6, acc[13]);

            csr = csr * cv;                      // cs7 = -c^7
            csP = pack2(csr, csr);
            unsigned long long gv7 = fma2(tp.x, gv6, gv5);    // +trp
            unsigned long long gw7 = fma2(tp.x, gw6, gw5);
            acc[14] = fma2(csP, gv7, acc[14]);
            acc[15] = fma2(csP, gw7, acc[15]);
        }
    }

    // ---- 2-stage tree reduction: (g2->g0, g3->g1), then g1->g0 ----
    if (grp == 2) {
#pragma unroll
        for (int m = 0; m < NPACK; m++) bufA[tg][m] = acc[m];
    } else if (grp == 3) {
#pragma unroll
        for (int m = 0; m < NPACK; m++) bufB[tg][m] = acc[m];
    }
    __syncthreads();

    if (grp == 0) {
#pragma unroll
        for (int m = 0; m < NPACK; m++) acc[m] = add2(acc[m], bufA[tg][m]);
    } else if (grp == 1) {
#pragma unroll
        for (int m = 0; m < NPACK; m++) acc[m] = add2(acc[m], bufB[tg][m]);
    }
    __syncthreads();

    if (grp == 1) {
#pragma unroll
        for (int m = 0; m < NPACK; m++) bufA[tg][m] = acc[m];
    }
    __syncthreads();

    if (grp == 0 && l0 < L) {
#pragma unroll
        for (int m = 0; m < NPACK; m++) acc[m] = add2(acc[m], bufA[tg][m]);

        float* Kout = out + (size_t)d * (size_t)L + l0;
        if (l0 + CHUNK <= L) {
#pragma unroll
            for (int m = 0; m < NPACK; m++) {
                *reinterpret_cast<unsigned long long*>(Kout + 2 * m) = acc[m];
            }
        } else {
#pragma unroll
            for (int m = 0; m < NPACK; m++) {
                float lo, hi;
                unpack2(acc[m], lo, hi);
                if (l0 + 2 * m     < L) Kout[2 * m]     = lo;
                if (l0 + 2 * m + 1 < L) Kout[2 * m + 1] = hi;
            }
        }
    }
}

extern "C" void kernel_launch(void* const* d_in, const int* in_sizes, int n_in,
                              void* d_out, int out_size)
{
    const float* Lre   = (const float*)d_in[0];
    const float* Lim   = (const float*)d_in[1];
    const float* Bre   = (const float*)d_in[2];
    const float* Bim   = (const float*)d_in[3];
    const float* Cre   = (const float*)d_in[4];
    const float* Cim   = (const float*)d_in[5];
    const float* Dp    = (const float*)d_in[6];
    const float* logdt = (const float*)d_in[7];
    float* out = (float*)d_out;

    const int d_model = in_sizes[6];                 // 512
    const int N = in_sizes[0] / d_model;             // 64
    const int L = (out_size - d_model) / d_model;    // 2048

    static int attrs_set = 0;
    if (!attrs_set) {
        cudaFuncSetAttribute(lssl_fold_kernel,
                             cudaFuncAttributePreferredSharedMemoryCarveout, 100);
        attrs_set = 1;
    }

    const int per_block_l = GSIZE * CHUNK;           // 1024
    const int gridy = (L + per_block_l - 1) / per_block_l;  // 2

    dim3 grid(d_model, gridy);
    size_t shm = (size_t)N * 4 * sizeof(float4);     // 64B per n = 4KB
    lssl_fold_kernel<<<grid, TPB, shm>>>(
        Lre, Lim, Bre, Bim, Cre, Cim, Dp, logdt, out, N, L, d_model);
}